// round 12
// baseline (speedup 1.0000x reference)
#include <cuda_runtime.h>
#include <cstdint>
#include <math.h>

#define N_B 64
#define T_T 512
#define D_D 512
#define H_H 512

// Scratch (device globals: allocation-free per harness rules)
__device__ float g_hbuf[2 * 8 * 8 * 512];   // double-buffered compact h exchange
__device__ unsigned int g_sync[8];          // per-group step counters

__global__ void init_sync_kernel() {
    if (threadIdx.x < 8) g_sync[threadIdx.x] = 0u;
}

// ---- packed fp32x2 helpers (Blackwell FFMA2 path) ----
__device__ __forceinline__ unsigned long long ffma2(
    unsigned long long a, unsigned long long b, unsigned long long c) {
    unsigned long long d;
    asm("fma.rn.f32x2 %0, %1, %2, %3;" : "=l"(d) : "l"(a), "l"(b), "l"(c));
    return d;
}
__device__ __forceinline__ unsigned long long pack2(float lo, float hi) {
    unsigned long long r;
    asm("mov.b64 %0, {%1, %2};" : "=l"(r) : "f"(lo), "f"(hi));
    return r;
}

// ---------------------------------------------------------------------------
// Fused RNN: 128 CTAs = 8 groups (8 batch rows) x 16 column slices (32 cols).
// Each CTA holds Wh[:,slice] AND Wx[:,slice] in SMEM (bank-staggered).
// Per step: h-slab on the critical path; x-slab for step t+1 computed in the
// barrier dead time; x tiles double-buffered, prefetched 2 steps ahead.
// ---------------------------------------------------------------------------
#define KPSTRIDE 1032            // 32k*32cols + 8 stagger floats per kp chunk
#define SW_F     (16 * KPSTRIDE) // 16512 floats per weight slice
#define HPAD     516
#define RPAD     288             // 8*36 reduction row per kp
#define SXB      (8 * HPAD)      // 4128 floats per x-tile buffer
#define SMEM_SCAN_BYTES ((2 * SW_F + 8 * HPAD + 16 * RPAD + 2 * SXB) * 4)

// 16-col x 32-k packed-FMA slab (8 f32x2 accumulators)
__device__ __forceinline__ void slab16x32(
    const float* __restrict__ vrow,      // 32 contiguous activations
    const float* __restrict__ wb,        // &sW[kp*KPSTRIDE + cg*16]
    unsigned long long* __restrict__ acc)
{
#pragma unroll 8
    for (int kk = 0; kk < 32; kk++) {
        float hv = vrow[kk];
        unsigned long long h2 = pack2(hv, hv);
        const float* wp = wb + (kk << 5);
        ulonglong2 wA = *(const ulonglong2*)(wp + 0);
        ulonglong2 wB = *(const ulonglong2*)(wp + 4);
        ulonglong2 wC = *(const ulonglong2*)(wp + 8);
        ulonglong2 wD = *(const ulonglong2*)(wp + 12);
        acc[0] = ffma2(h2, wA.x, acc[0]);
        acc[1] = ffma2(h2, wA.y, acc[1]);
        acc[2] = ffma2(h2, wB.x, acc[2]);
        acc[3] = ffma2(h2, wB.y, acc[3]);
        acc[4] = ffma2(h2, wC.x, acc[4]);
        acc[5] = ffma2(h2, wC.y, acc[5]);
        acc[6] = ffma2(h2, wD.x, acc[6]);
        acc[7] = ffma2(h2, wD.y, acc[7]);
    }
}

__global__ __launch_bounds__(256, 1) void rnn_fused_kernel(
    const float* __restrict__ x,    // (64, 512, 512)
    const float* __restrict__ h0,   // (64, 512)
    const float* __restrict__ Wh,   // (512, 512)
    const float* __restrict__ Wx,   // (512, 512)
    const float* __restrict__ bias, // (512,)
    float* __restrict__ out)        // (64, 512, 512)
{
    extern __shared__ float smem[];
    float* sWh  = smem;                     // [16 kp][32 k][32 cols] stride 1032
    float* sWx  = sWh + SW_F;
    float* sH   = sWx + SW_F;               // [8][516]
    float* sRed = sH + 8 * HPAD;            // [16][8][36]
    float* sX   = sRed + 16 * RPAD;         // [2][8][516]

    const int tid = threadIdx.x;
    const int g   = blockIdx.x >> 4;        // batch group 0..7
    const int c   = blockIdx.x & 15;        // column slice 0..15
    const int c0  = c << 5;
    const int n0  = g << 3;

    // Load both weight slices into staggered layout
    for (int i = tid; i < 4096; i += 256) {
        int k = i >> 3, j4 = (i & 7) << 2;
        int d = (k >> 5) * KPSTRIDE + (k & 31) * 32 + j4;
        *(float4*)&sWh[d] = *(const float4*)&Wh[(size_t)k * H_H + c0 + j4];
        *(float4*)&sWx[d] = *(const float4*)&Wx[(size_t)k * H_H + c0 + j4];
    }
    // Prefetch x tile for t=0 into buffer 0
    for (int i = tid; i < 1024; i += 256) {
        int rr = i >> 7, q = (i & 127) << 2;
        *(float4*)&sX[rr * HPAD + q] =
            __ldcg((const float4*)&x[((size_t)(n0 + rr) * T_T + 0) * D_D + q]);
    }

    const int r   = tid & 7;                // batch row for slab
    const int cg  = (tid >> 3) & 1;         // column half (16 cols)
    const int kp  = tid >> 4;               // k-split 0..15
    const int or_ = tid >> 5;               // owned output row
    const int oc_ = tid & 31;               // owned output col

    const float bcol = bias[c0 + oc_];
    size_t oidx = ((size_t)(n0 + or_) * T_T) * H_H + c0 + oc_;

    const float* whb = &sWh[kp * KPSTRIDE + (cg << 4)];
    const float* wxb = &sWx[kp * KPSTRIDE + (cg << 4)];
    unsigned int* syncp = &g_sync[g];

    __syncthreads();

    // x-slab for t=0
    unsigned long long xacc[8];
#pragma unroll
    for (int j = 0; j < 8; j++) xacc[j] = 0ull;
    slab16x32(&sX[r * HPAD + (kp << 5)], wxb, xacc);

    // Prefetch x tile for t=1 into buffer 1 (visible after next __syncthreads)
    for (int i = tid; i < 1024; i += 256) {
        int rr = i >> 7, q = (i & 127) << 2;
        *(float4*)&sX[SXB + rr * HPAD + q] =
            __ldcg((const float4*)&x[((size_t)(n0 + rr) * T_T + 1) * D_D + q]);
    }

    for (int t = 0; t < T_T; t++) {
        // ---- load h_{t-1} (contiguous 16 KB block) ----
        {
            const float4* hb = (t == 0)
                ? (const float4*)(h0 + (size_t)n0 * H_H)
                : (const float4*)(g_hbuf + (size_t)((((t - 1) & 1) << 3) + g) * 4096);
#pragma unroll
            for (int i = tid; i < 1024; i += 256) {
                float4 v = __ldcg(hb + i);
                *(float4*)&sH[(i >> 7) * HPAD + ((i & 127) << 2)] = v;
            }
        }
        __syncthreads();

        // ---- h-slab (critical path) ----
        unsigned long long acc[8];
#pragma unroll
        for (int j = 0; j < 8; j++) acc[j] = xacc[j];
        slab16x32(&sH[r * HPAD + (kp << 5)], whb, acc);

        // ---- write combined k-split partials ----
        {
            float* dst = &sRed[kp * RPAD + r * 36 + (cg << 4)];
            *(ulonglong2*)(dst + 0)  = make_ulonglong2(acc[0], acc[1]);
            *(ulonglong2*)(dst + 4)  = make_ulonglong2(acc[2], acc[3]);
            *(ulonglong2*)(dst + 8)  = make_ulonglong2(acc[4], acc[5]);
            *(ulonglong2*)(dst + 12) = make_ulonglong2(acc[6], acc[7]);
        }
        __syncthreads();

        // ---- reduce 16 partials (fixed order), bias, tanh, store ----
        float v = bcol;
#pragma unroll
        for (int p = 0; p < 16; p++)
            v += sRed[p * RPAD + or_ * 36 + oc_];
        v = tanhf(v);
        out[oidx] = v;
        oidx += H_H;

        if (t < T_T - 1) {
            // publish h_t to exchange buffer (parity t&1)
            g_hbuf[(size_t)(((t & 1) << 3) + g) * 4096 + (or_ << 9) + c0 + oc_] = v;
            if (tid == 0) {
                asm volatile("red.release.gpu.global.add.u32 [%0], %1;"
                             :: "l"(syncp), "r"(1u) : "memory");
            }

            // ======== dead-time work: x-slab for t+1 ========
            // sX[(t+1)&1] was written in iter t-1 (or prologue), synced since.
#pragma unroll
            for (int j = 0; j < 8; j++) xacc[j] = 0ull;
            slab16x32(&sX[((t + 1) & 1) * SXB + r * HPAD + (kp << 5)], wxb, xacc);

            // prefetch x tile t+2 into sX[t&1] (read again only in iter t+1)
            if (t + 2 < T_T) {
                const size_t tb = (size_t)(t + 2) * D_D;
#pragma unroll
                for (int i = tid; i < 1024; i += 256) {
                    int rr = i >> 7, q = (i & 127) << 2;
                    *(float4*)&sX[(t & 1) * SXB + rr * HPAD + q] =
                        __ldcg((const float4*)&x[(size_t)(n0 + rr) * T_T * D_D + tb + q]);
                }
            }
            // ================================================

            if (tid == 0) {
                const unsigned int target = (unsigned int)(t + 1) << 4;
                unsigned int fv;
                do {
                    asm volatile("ld.acquire.gpu.global.u32 %0, [%1];"
                                 : "=r"(fv) : "l"(syncp) : "memory");
                } while (fv < target);
            }
            __syncthreads();
        }
    }
}

// ---------------------------------------------------------------------------
extern "C" void kernel_launch(void* const* d_in, const int* in_sizes, int n_in,
                              void* d_out, int out_size) {
    (void)in_sizes; (void)n_in; (void)out_size;
    const float* x  = (const float*)d_in[0];
    const float* h0 = (const float*)d_in[1];
    const float* Wx = (const float*)d_in[2];
    const float* Wh = (const float*)d_in[3];
    const float* b  = (const float*)d_in[4];
    float* out = (float*)d_out;

    init_sync_kernel<<<1, 32>>>();

    cudaFuncSetAttribute((const void*)rnn_fused_kernel,
                         cudaFuncAttributeMaxDynamicSharedMemorySize,
                         SMEM_SCAN_BYTES);
    rnn_fused_kernel<<<128, 256, SMEM_SCAN_BYTES>>>(x, h0, Wh, Wx, b, out);
}